// round 3
// baseline (speedup 1.0000x reference)
#include <cuda_runtime.h>
#include <math.h>

#define NB 16
#define GN 4096
#define GK 256

// ---------------- scratch (allocation-free: device globals) ----------------
__device__ float g_qkv[NB * 768 * 4096];   // [b][o][n]  (q rows 0-255, k 256-511, v 512-767)
__device__ float g_ctxp[16 * 64 * 4096];   // [split][bh][d*64+e] partial contexts
__device__ float g_M[NB * 256 * 256];      // folded weight M_b[o][c]
__device__ float g_kmax[NB * 256];
__device__ float g_kinv[NB * 256];

// ---------------- shared 128x128x8 fp32 SGEMM body (N=4096, K=256) ---------
__device__ __forceinline__ void sgemm_body(
    const float* __restrict__ A, int aBatch,
    const float* __restrict__ B, int bBatch,
    float* __restrict__ C, int cBatch,
    const float* __restrict__ bias)
{
    const int bz = blockIdx.z;
    A += (size_t)bz * aBatch;
    B += (size_t)bz * bBatch;
    C += (size_t)bz * cBatch;

    const int n0 = blockIdx.x * 128;
    const int m0 = blockIdx.y * 128;
    const int t  = threadIdx.x;
    const int tx = t & 15;
    const int ty = t >> 4;

    __shared__ float As[8][128];
    __shared__ float Bs[8][128];

    float acc[8][8];
#pragma unroll
    for (int i = 0; i < 8; i++)
#pragma unroll
        for (int j = 0; j < 8; j++) acc[i][j] = 0.f;

    const int am = t >> 1;          // 0..127 (m within tile)
    const int ak = (t & 1) * 4;     // 0 or 4 (k within tile)
    const int bk = t >> 5;          // 0..7
    const int bn = (t & 31) * 4;    // 0..124

    for (int k0 = 0; k0 < GK; k0 += 8) {
        float4 av = *(const float4*)(A + (size_t)(m0 + am) * GK + k0 + ak);
        float4 bv = *(const float4*)(B + (size_t)(k0 + bk) * GN + n0 + bn);
        __syncthreads();
        As[ak + 0][am] = av.x;
        As[ak + 1][am] = av.y;
        As[ak + 2][am] = av.z;
        As[ak + 3][am] = av.w;
        *(float4*)&Bs[bk][bn] = bv;
        __syncthreads();
#pragma unroll
        for (int kk = 0; kk < 8; kk++) {
            float4 a0 = *(const float4*)&As[kk][ty * 4];
            float4 a1 = *(const float4*)&As[kk][64 + ty * 4];
            float4 b0 = *(const float4*)&Bs[kk][tx * 4];
            float4 b1 = *(const float4*)&Bs[kk][64 + tx * 4];
            float ar[8] = {a0.x, a0.y, a0.z, a0.w, a1.x, a1.y, a1.z, a1.w};
            float br[8] = {b0.x, b0.y, b0.z, b0.w, b1.x, b1.y, b1.z, b1.w};
#pragma unroll
            for (int i = 0; i < 8; i++)
#pragma unroll
                for (int j = 0; j < 8; j++)
                    acc[i][j] = fmaf(ar[i], br[j], acc[i][j]);
        }
    }

#pragma unroll
    for (int i = 0; i < 8; i++) {
        int m = m0 + ((i < 4) ? (ty * 4 + i) : (64 + ty * 4 + (i - 4)));
        float bsv = bias ? bias[m] : 0.f;
        float4 o0 = make_float4(acc[i][0] + bsv, acc[i][1] + bsv, acc[i][2] + bsv, acc[i][3] + bsv);
        float4 o1 = make_float4(acc[i][4] + bsv, acc[i][5] + bsv, acc[i][6] + bsv, acc[i][7] + bsv);
        *(float4*)(C + (size_t)m * GN + n0 + tx * 4)      = o0;
        *(float4*)(C + (size_t)m * GN + n0 + 64 + tx * 4) = o1;
    }
}

// K1: qkv[b] = w_qkv(768x256) @ x[b](256x4096)
__global__ __launch_bounds__(256, 2) void qkv_gemm(const float* __restrict__ x,
                                                   const float* __restrict__ w_qkv) {
    sgemm_body(w_qkv, 0, x, 256 * GN, g_qkv, 768 * GN, nullptr);
}

// K6: Y[b] = M_b(256x256) @ qnorm[b](256x4096) + bias
__global__ __launch_bounds__(256, 2) void out_gemm(float* __restrict__ out,
                                                   const float* __restrict__ b_out) {
    sgemm_body(g_M, 256 * 256, g_qkv, 768 * GN, out, 256 * GN, b_out);
}

// K2: per k-row (b,h,d): max and 1/sum(exp) over n=4096
__global__ __launch_bounds__(256) void kstats_kernel() {
    int row = blockIdx.x;           // 0..4095 : b = row>>8, hd = row&255
    int b = row >> 8, hd = row & 255;
    const float* kp = g_qkv + ((size_t)(b * 768 + 256 + hd)) * GN;
    __shared__ float sm[256];
    int t = threadIdx.x;
    float m = -1e30f;
    for (int i = t; i < 1024; i += 256) {
        float4 v = *(const float4*)(kp + i * 4);
        m = fmaxf(m, fmaxf(fmaxf(v.x, v.y), fmaxf(v.z, v.w)));
    }
    sm[t] = m; __syncthreads();
    for (int s = 128; s > 0; s >>= 1) { if (t < s) sm[t] = fmaxf(sm[t], sm[t + s]); __syncthreads(); }
    m = sm[0]; __syncthreads();
    float ssum = 0.f;
    for (int i = t; i < 1024; i += 256) {
        float4 v = *(const float4*)(kp + i * 4);
        ssum += expf(v.x - m) + expf(v.y - m) + expf(v.z - m) + expf(v.w - m);
    }
    sm[t] = ssum; __syncthreads();
    for (int s = 128; s > 0; s >>= 1) { if (t < s) sm[t] += sm[t + s]; __syncthreads(); }
    if (t == 0) { g_kmax[row] = m; g_kinv[row] = 1.f / sm[0]; }
}

// K3: partial context over n-split s: ctxp[s][bh][d][e] = sum_{n in split} knorm[d,n]*v[e,n]
__global__ __launch_bounds__(256) void ctx_kernel() {
    int s  = blockIdx.x;  // 0..15
    int bh = blockIdx.y;  // 0..63
    int b = bh >> 2, h = bh & 3;
    const float* kb = g_qkv + ((size_t)(b * 768 + 256 + h * 64)) * GN + s * 256;
    const float* vb = g_qkv + ((size_t)(b * 768 + 512 + h * 64)) * GN + s * 256;
    __shared__ float ks[64][33];
    __shared__ float vs[64][33];
    int t = threadIdx.x;
    int tx = t & 15, ty = t >> 4;
    float acc[4][4];
#pragma unroll
    for (int i = 0; i < 4; i++)
#pragma unroll
        for (int j = 0; j < 4; j++) acc[i][j] = 0.f;

    for (int c = 0; c < 256; c += 32) {
        __syncthreads();
        for (int i = t; i < 512; i += 256) {
            int d = i >> 3, nn = (i & 7) * 4;
            float4 kv = *(const float4*)(kb + (size_t)d * GN + c + nn);
            float mx = g_kmax[bh * 64 + d], iv = g_kinv[bh * 64 + d];
            ks[d][nn + 0] = expf(kv.x - mx) * iv;
            ks[d][nn + 1] = expf(kv.y - mx) * iv;
            ks[d][nn + 2] = expf(kv.z - mx) * iv;
            ks[d][nn + 3] = expf(kv.w - mx) * iv;
            float4 vv = *(const float4*)(vb + (size_t)d * GN + c + nn);
            vs[d][nn + 0] = vv.x; vs[d][nn + 1] = vv.y;
            vs[d][nn + 2] = vv.z; vs[d][nn + 3] = vv.w;
        }
        __syncthreads();
#pragma unroll 8
        for (int nn = 0; nn < 32; nn++) {
            float ar[4], br[4];
#pragma unroll
            for (int i = 0; i < 4; i++) ar[i] = ks[ty * 4 + i][nn];
#pragma unroll
            for (int j = 0; j < 4; j++) br[j] = vs[tx * 4 + j][nn];
#pragma unroll
            for (int i = 0; i < 4; i++)
#pragma unroll
                for (int j = 0; j < 4; j++)
                    acc[i][j] = fmaf(ar[i], br[j], acc[i][j]);
        }
    }
    float* cp = g_ctxp + ((size_t)(s * 64 + bh)) * 4096;
#pragma unroll
    for (int i = 0; i < 4; i++)
        *(float4*)(cp + (ty * 4 + i) * 64 + tx * 4) =
            make_float4(acc[i][0], acc[i][1], acc[i][2], acc[i][3]);
}

// K4: fold context into output weight: M_b[o][h*64+d] = sum_e W_out[o][h*64+e]*ctx[b,h,d,e]
__global__ __launch_bounds__(256) void mmat_kernel(const float* __restrict__ w_out) {
    int bh = blockIdx.x, b = bh >> 2, h = bh & 3;
    __shared__ float ctx[64][65];
    int t = threadIdx.x;
    for (int i = t; i < 4096; i += 256) {
        float ssum = 0.f;
#pragma unroll
        for (int sp = 0; sp < 16; sp++) ssum += g_ctxp[((size_t)(sp * 64 + bh)) * 4096 + i];
        ctx[i >> 6][i & 63] = ssum;
    }
    __syncthreads();
    int o = t;  // 0..255
    float w[64];
    const float* wp = w_out + o * 256 + h * 64;
#pragma unroll
    for (int e = 0; e < 64; e += 4) {
        float4 v = *(const float4*)(wp + e);
        w[e] = v.x; w[e + 1] = v.y; w[e + 2] = v.z; w[e + 3] = v.w;
    }
    float* Mp = g_M + (size_t)b * 65536 + o * 256 + h * 64;
#pragma unroll 2
    for (int d = 0; d < 64; d++) {
        float a = 0.f;
#pragma unroll
        for (int e = 0; e < 64; e++) a = fmaf(w[e], ctx[d][e], a);
        Mp[d] = a;
    }
}

// K5: in-place q softmax over d (within each head's 64 rows), times SCALE=0.125
__global__ __launch_bounds__(256) void qnorm_kernel() {
    int nt = blockIdx.x;  // 0..63 (n tile of 64)
    int bh = blockIdx.y;  // 0..63
    int b = bh >> 2, h = bh & 3;
    float* qb = g_qkv + ((size_t)(b * 768 + h * 64)) * GN + nt * 64;
    __shared__ float tile[64][68];
    __shared__ float red[4][64];
    __shared__ float cmax[64];
    __shared__ float cfac[64];
    int t = threadIdx.x;
    int d = t >> 2, c0 = (t & 3) * 16;
#pragma unroll
    for (int i = 0; i < 4; i++) {
        float4 v = *(const float4*)(qb + (size_t)d * GN + c0 + i * 4);
        *(float4*)&tile[d][c0 + i * 4] = v;
    }
    __syncthreads();
    int col = t & 63, seg = t >> 6;
    float m = -1e30f;
    for (int r = seg * 16; r < seg * 16 + 16; r++) m = fmaxf(m, tile[r][col]);
    red[seg][col] = m;
    __syncthreads();
    if (seg == 0)
        cmax[col] = fmaxf(fmaxf(red[0][col], red[1][col]), fmaxf(red[2][col], red[3][col]));
    __syncthreads();
    float mm = cmax[col];
    float ssum = 0.f;
    for (int r = seg * 16; r < seg * 16 + 16; r++) {
        float e = expf(tile[r][col] - mm);
        tile[r][col] = e;
        ssum += e;
    }
    red[seg][col] = ssum;
    __syncthreads();
    if (seg == 0)
        cfac[col] = 0.125f / (red[0][col] + red[1][col] + red[2][col] + red[3][col]);
    __syncthreads();
#pragma unroll
    for (int i = 0; i < 4; i++) {
        int c = c0 + i * 4;
        float4 v = *(float4*)&tile[d][c];
        v.x *= cfac[c]; v.y *= cfac[c + 1]; v.z *= cfac[c + 2]; v.w *= cfac[c + 3];
        *(float4*)(qb + (size_t)d * GN + c) = v;
    }
}

extern "C" void kernel_launch(void* const* d_in, const int* in_sizes, int n_in,
                              void* d_out, int out_size) {
    const float* x     = (const float*)d_in[0];
    const float* w_qkv = (const float*)d_in[1];
    const float* w_out = (const float*)d_in[2];
    const float* b_out = (const float*)d_in[3];
    float* out = (float*)d_out;

    qkv_gemm<<<dim3(32, 6, NB), 256>>>(x, w_qkv);     // 25.8 GFLOP
    kstats_kernel<<<4096, 256>>>();                   // k softmax stats
    ctx_kernel<<<dim3(16, 64), 256>>>();              // 2.15 GFLOP, deterministic split-sum
    mmat_kernel<<<64, 256>>>(w_out);                  // fold ctx into W_out
    qnorm_kernel<<<dim3(64, 64), 256>>>();            // q softmax in place
    out_gemm<<<dim3(32, 2, NB), 256>>>(out, b_out);   // 8.6 GFLOP + bias
}

// round 9
// speedup vs baseline: 1.4529x; 1.4529x over previous
#include <cuda_runtime.h>
#include <math.h>
#include <stdint.h>

#define NB 16
#define GN 4096

// ---------------- scratch (allocation-free: device globals) ----------------
__device__ float g_qkv[NB * 768 * 4096];   // [b][o][n]  (q 0-255 — q-hat in place, k 256-511, v 512-767)
__device__ float g_ctxp[16 * 64 * 4096];   // [split][bh][d*64+e]
__device__ float g_M[NB * 256 * 256];      // folded weight
__device__ float g_kmax[NB * 256];
__device__ float g_kinv[NB * 256];

// ---------------- tf32 helpers (target-portable: no 'a'-suffix features) ----
__device__ __forceinline__ uint32_t f2tf32(float f) {
    uint32_t u;
    asm("cvt.rna.tf32.f32 %0, %1;" : "=r"(u) : "f"(f));
    return u;
}
__device__ __forceinline__ void mma_tf32(float* d, const uint32_t* a, const uint32_t* bb) {
    asm volatile(
        "mma.sync.aligned.m16n8k8.row.col.f32.tf32.tf32.f32 "
        "{%0,%1,%2,%3}, {%4,%5,%6,%7}, {%8,%9}, {%0,%1,%2,%3};"
        : "+f"(d[0]), "+f"(d[1]), "+f"(d[2]), "+f"(d[3])
        : "r"(a[0]), "r"(a[1]), "r"(a[2]), "r"(a[3]), "r"(bb[0]), "r"(bb[1]));
}

#define LDA 36    // A smem row stride
#define LDB 132   // B smem row stride
#define ASZ (128 * LDA)
#define BSZ (32 * LDB)
#define TCG_SMEM ((2 * ASZ + 2 * BSZ) * 4)   // 70656 B dynamic

// C[M,4096] = A[M,256] @ B[256,4096]  (tf32 tensor cores)
// mode 0: A=w_qkv[768,256], B=x[b], C=g_qkv        mode 1: A=g_M[b], B=q-hat rows of g_qkv, C=out +bias
__global__ __launch_bounds__(256, 2) void tc_gemm(int mode,
                                                  const float* __restrict__ w,
                                                  const float* __restrict__ xp,
                                                  float* __restrict__ outp,
                                                  const float* __restrict__ bias) {
    extern __shared__ float smem[];
    float* As = smem;               // [2][128][LDA]
    float* Bs = smem + 2 * ASZ;     // [2][32][LDB]

    const int t = threadIdx.x;
    const int lid = t & 31, wid = t >> 5;
    const int wm = wid >> 1, wn = wid & 1;
    const int gid = lid >> 2, tig = lid & 3;
    const int b = blockIdx.z, n0 = blockIdx.x * 128, m0 = blockIdx.y * 128;

    const float* A;
    const float* B;
    float* C;
    if (mode == 0) {
        A = w + (size_t)m0 * 256;
        B = xp + (size_t)b * (256ull * 4096) + n0;
        C = g_qkv + (size_t)b * (768ull * 4096) + (size_t)m0 * 4096 + n0;
    } else {
        A = g_M + (size_t)b * 65536 + (size_t)m0 * 256;
        B = g_qkv + (size_t)b * (768ull * 4096) + n0;   // q-hat rows 0..255
        C = outp + (size_t)b * (256ull * 4096) + (size_t)m0 * 4096 + n0;
    }

    // global-load mapping
    const int ar = t >> 1, ac = (t & 1) * 16;   // A: 128 rows x 32 k
    const int bk = t >> 3, bc = (t & 7) * 16;   // B: 32 k x 128 n

    float acc[2][8][4];
#pragma unroll
    for (int mi = 0; mi < 2; mi++)
#pragma unroll
        for (int nj = 0; nj < 8; nj++)
#pragma unroll
            for (int q = 0; q < 4; q++) acc[mi][nj][q] = 0.f;

    // preload chunk 0
    {
        const float* ap = A + (size_t)ar * 256 + ac;
        const float* bp = B + (size_t)bk * 4096;
#pragma unroll
        for (int i = 0; i < 4; i++) {
            float4 v = *(const float4*)(ap + i * 4);
            float* d = As + ar * LDA + ac + i * 4;
            d[0] = __uint_as_float(f2tf32(v.x)); d[1] = __uint_as_float(f2tf32(v.y));
            d[2] = __uint_as_float(f2tf32(v.z)); d[3] = __uint_as_float(f2tf32(v.w));
        }
#pragma unroll
        for (int i = 0; i < 4; i++) {
            float4 v = *(const float4*)(bp + bc + i * 4);
            float* d = Bs + bk * LDB + bc + i * 4;
            d[0] = __uint_as_float(f2tf32(v.x)); d[1] = __uint_as_float(f2tf32(v.y));
            d[2] = __uint_as_float(f2tf32(v.z)); d[3] = __uint_as_float(f2tf32(v.w));
        }
    }
    __syncthreads();

    for (int c = 0; c < 8; c++) {
        const int s = c & 1;
        float4 av[4], bv[4];
        if (c < 7) {
            const int k0 = (c + 1) * 32;
            const float* ap = A + (size_t)ar * 256 + k0 + ac;
            const float* bp = B + (size_t)(k0 + bk) * 4096;
#pragma unroll
            for (int i = 0; i < 4; i++) av[i] = *(const float4*)(ap + i * 4);
#pragma unroll
            for (int i = 0; i < 4; i++) bv[i] = *(const float4*)(bp + bc + i * 4);
        }
        // compute on buffer s
        const float* Ac = As + s * ASZ;
        const float* Bc = Bs + s * BSZ;
#pragma unroll
        for (int ks = 0; ks < 4; ks++) {
            const int kk = ks * 8;
            uint32_t af[2][4];
#pragma unroll
            for (int mi = 0; mi < 2; mi++) {
                const float* ab = Ac + (wm * 32 + mi * 16 + gid) * LDA + kk + tig;
                af[mi][0] = __float_as_uint(ab[0]);
                af[mi][1] = __float_as_uint(ab[8 * LDA]);
                af[mi][2] = __float_as_uint(ab[4]);
                af[mi][3] = __float_as_uint(ab[8 * LDA + 4]);
            }
#pragma unroll
            for (int nj = 0; nj < 8; nj++) {
                const float* bb = Bc + (kk + tig) * LDB + wn * 64 + nj * 8 + gid;
                uint32_t bf[2];
                bf[0] = __float_as_uint(bb[0]);
                bf[1] = __float_as_uint(bb[4 * LDB]);
                mma_tf32(acc[0][nj], af[0], bf);
                mma_tf32(acc[1][nj], af[1], bf);
            }
        }
        if (c < 7) {
            const int s2 = (c + 1) & 1;
            float* da = As + s2 * ASZ + ar * LDA + ac;
            float* db = Bs + s2 * BSZ + bk * LDB + bc;
#pragma unroll
            for (int i = 0; i < 4; i++) {
                da[i * 4 + 0] = __uint_as_float(f2tf32(av[i].x));
                da[i * 4 + 1] = __uint_as_float(f2tf32(av[i].y));
                da[i * 4 + 2] = __uint_as_float(f2tf32(av[i].z));
                da[i * 4 + 3] = __uint_as_float(f2tf32(av[i].w));
            }
#pragma unroll
            for (int i = 0; i < 4; i++) {
                db[i * 4 + 0] = __uint_as_float(f2tf32(bv[i].x));
                db[i * 4 + 1] = __uint_as_float(f2tf32(bv[i].y));
                db[i * 4 + 2] = __uint_as_float(f2tf32(bv[i].z));
                db[i * 4 + 3] = __uint_as_float(f2tf32(bv[i].w));
            }
            __syncthreads();
        }
    }

    // ---- epilogue: stage C tile in smem, coalesced float4 out ----
    __syncthreads();
    float* Cs = smem;   // 128 x LDB reuse (128*132*4 = 67.6KB <= 70.6KB)
#pragma unroll
    for (int mi = 0; mi < 2; mi++)
#pragma unroll
        for (int nj = 0; nj < 8; nj++) {
            int row = wm * 32 + mi * 16 + gid;
            int col = wn * 64 + nj * 8 + 2 * tig;
            Cs[row * LDB + col]           = acc[mi][nj][0];
            Cs[row * LDB + col + 1]       = acc[mi][nj][1];
            Cs[(row + 8) * LDB + col]     = acc[mi][nj][2];
            Cs[(row + 8) * LDB + col + 1] = acc[mi][nj][3];
        }
    __syncthreads();
    {
        const int r = t >> 1, h = (t & 1) * 64;
        const float bsv = bias ? bias[m0 + r] : 0.f;
        float* crow = C + (size_t)r * 4096 + h;
        const float* srow = Cs + r * LDB + h;
#pragma unroll
        for (int j = 0; j < 16; j++) {
            float4 v = *(const float4*)(srow + j * 4);
            v.x += bsv; v.y += bsv; v.z += bsv; v.w += bsv;
            *(float4*)(crow + j * 4) = v;
        }
    }
}

// ---------------- K2: k-row softmax stats ----------------
__global__ __launch_bounds__(256) void kstats_kernel() {
    int row = blockIdx.x;
    int b = row >> 8, hd = row & 255;
    const float* kp = g_qkv + ((size_t)(b * 768 + 256 + hd)) * GN;
    __shared__ float sm[256];
    int t = threadIdx.x;
    float m = -1e30f;
    for (int i = t; i < 1024; i += 256) {
        float4 v = *(const float4*)(kp + i * 4);
        m = fmaxf(m, fmaxf(fmaxf(v.x, v.y), fmaxf(v.z, v.w)));
    }
    sm[t] = m; __syncthreads();
    for (int s = 128; s > 0; s >>= 1) { if (t < s) sm[t] = fmaxf(sm[t], sm[t + s]); __syncthreads(); }
    m = sm[0]; __syncthreads();
    float ssum = 0.f;
    for (int i = t; i < 1024; i += 256) {
        float4 v = *(const float4*)(kp + i * 4);
        ssum += expf(v.x - m) + expf(v.y - m) + expf(v.z - m) + expf(v.w - m);
    }
    sm[t] = ssum; __syncthreads();
    for (int s = 128; s > 0; s >>= 1) { if (t < s) sm[t] += sm[t + s]; __syncthreads(); }
    if (t == 0) { g_kmax[row] = m; g_kinv[row] = 1.f / sm[0]; }
}

// ---------------- K3: partial contexts (16-way deterministic split) ----------------
__global__ __launch_bounds__(256) void ctx_kernel() {
    int s = blockIdx.x, bh = blockIdx.y;
    int b = bh >> 2, h = bh & 3;
    const float* kb = g_qkv + ((size_t)(b * 768 + 256 + h * 64)) * GN + s * 256;
    const float* vb = g_qkv + ((size_t)(b * 768 + 512 + h * 64)) * GN + s * 256;
    __shared__ float ks[64][33];
    __shared__ float vs[64][33];
    int t = threadIdx.x;
    int tx = t & 15, ty = t >> 4;
    float acc[4][4];
#pragma unroll
    for (int i = 0; i < 4; i++)
#pragma unroll
        for (int j = 0; j < 4; j++) acc[i][j] = 0.f;

    for (int c = 0; c < 256; c += 32) {
        __syncthreads();
        for (int i = t; i < 512; i += 256) {
            int d = i >> 3, nn = (i & 7) * 4;
            float4 kv = *(const float4*)(kb + (size_t)d * GN + c + nn);
            float mx = g_kmax[bh * 64 + d], iv = g_kinv[bh * 64 + d];
            ks[d][nn + 0] = expf(kv.x - mx) * iv;
            ks[d][nn + 1] = expf(kv.y - mx) * iv;
            ks[d][nn + 2] = expf(kv.z - mx) * iv;
            ks[d][nn + 3] = expf(kv.w - mx) * iv;
            float4 vv = *(const float4*)(vb + (size_t)d * GN + c + nn);
            vs[d][nn + 0] = vv.x; vs[d][nn + 1] = vv.y;
            vs[d][nn + 2] = vv.z; vs[d][nn + 3] = vv.w;
        }
        __syncthreads();
#pragma unroll 8
        for (int nn = 0; nn < 32; nn++) {
            float ar[4], br[4];
#pragma unroll
            for (int i = 0; i < 4; i++) ar[i] = ks[ty * 4 + i][nn];
#pragma unroll
            for (int j = 0; j < 4; j++) br[j] = vs[tx * 4 + j][nn];
#pragma unroll
            for (int i = 0; i < 4; i++)
#pragma unroll
                for (int j = 0; j < 4; j++)
                    acc[i][j] = fmaf(ar[i], br[j], acc[i][j]);
        }
    }
    float* cp = g_ctxp + ((size_t)(s * 64 + bh)) * 4096;
#pragma unroll
    for (int i = 0; i < 4; i++)
        *(float4*)(cp + (ty * 4 + i) * 64 + tx * 4) =
            make_float4(acc[i][0], acc[i][1], acc[i][2], acc[i][3]);
}

// ---------------- K4: fold ctx into W_out ----------------
__global__ __launch_bounds__(256) void mmat_kernel(const float* __restrict__ w_out) {
    int oq = blockIdx.x, bh = blockIdx.y;
    int b = bh >> 2, h = bh & 3;
    __shared__ float ctx[64][65];
    int t = threadIdx.x;
    for (int i = t; i < 4096; i += 256) {
        float ssum = 0.f;
#pragma unroll
        for (int sp = 0; sp < 16; sp++) ssum += g_ctxp[((size_t)(sp * 64 + bh)) * 4096 + i];
        ctx[i >> 6][i & 63] = ssum;
    }
    __syncthreads();
    int o = oq * 64 + (t >> 2);
    int d0 = (t & 3) * 16;
    float w[64];
    const float* wp = w_out + o * 256 + h * 64;
#pragma unroll
    for (int e = 0; e < 64; e += 4) {
        float4 v = *(const float4*)(wp + e);
        w[e] = v.x; w[e + 1] = v.y; w[e + 2] = v.z; w[e + 3] = v.w;
    }
    float* Mp = g_M + (size_t)b * 65536 + o * 256 + h * 64;
    for (int d = d0; d < d0 + 16; d++) {
        float a = 0.f;
#pragma unroll
        for (int e = 0; e < 64; e++) a = fmaf(w[e], ctx[d][e], a);
        Mp[d] = a;
    }
}

// ---------------- K5: q softmax over d, in place, times SCALE ----------------
__global__ __launch_bounds__(256) void qnorm_kernel() {
    int nt = blockIdx.x;  // 0..63
    int bh = blockIdx.y;  // 0..63
    int b = bh >> 2, h = bh & 3;
    float* qb = g_qkv + ((size_t)(b * 768 + h * 64)) * GN + nt * 64;
    __shared__ float tile[64][68];
    __shared__ float red[4][64];
    __shared__ float cmax[64];
    __shared__ float cfac[64];
    int t = threadIdx.x;
    int d = t >> 2, c0 = (t & 3) * 16;
#pragma unroll
    for (int i = 0; i < 4; i++) {
        float4 v = *(const float4*)(qb + (size_t)d * GN + c0 + i * 4);
        *(float4*)&tile[d][c0 + i * 4] = v;
    }
    __syncthreads();
    int col = t & 63, seg = t >> 6;
    float m = -1e30f;
    for (int r = seg * 16; r < seg * 16 + 16; r++) m = fmaxf(m, tile[r][col]);
    red[seg][col] = m;
    __syncthreads();
    if (seg == 0)
        cmax[col] = fmaxf(fmaxf(red[0][col], red[1][col]), fmaxf(red[2][col], red[3][col]));
    __syncthreads();
    float mm = cmax[col];
    float ssum = 0.f;
    for (int r = seg * 16; r < seg * 16 + 16; r++) {
        float e = expf(tile[r][col] - mm);
        tile[r][col] = e;
        ssum += e;
    }
    red[seg][col] = ssum;
    __syncthreads();
    if (seg == 0)
        cfac[col] = 0.125f / (red[0][col] + red[1][col] + red[2][col] + red[3][col]);
    __syncthreads();
#pragma unroll
    for (int i = 0; i < 4; i++) {
        int c = c0 + i * 4;
        float4 v = *(float4*)&tile[d][c];
        v.x *= cfac[c]; v.y *= cfac[c + 1]; v.z *= cfac[c + 2]; v.w *= cfac[c + 3];
        *(float4*)(qb + (size_t)d * GN + c) = v;
    }
}

extern "C" void kernel_launch(void* const* d_in, const int* in_sizes, int n_in,
                              void* d_out, int out_size) {
    const float* x     = (const float*)d_in[0];
    const float* w_qkv = (const float*)d_in[1];
    const float* w_out = (const float*)d_in[2];
    const float* b_out = (const float*)d_in[3];
    float* out = (float*)d_out;

    cudaFuncSetAttribute(tc_gemm, cudaFuncAttributeMaxDynamicSharedMemorySize, TCG_SMEM);

    tc_gemm<<<dim3(32, 6, NB), 256, TCG_SMEM>>>(0, w_qkv, x, nullptr, nullptr);  // qkv (tf32 TC)
    kstats_kernel<<<4096, 256>>>();
    ctx_kernel<<<dim3(16, 64), 256>>>();
    mmat_kernel<<<dim3(4, 64), 256>>>(w_out);
    qnorm_kernel<<<dim3(64, 64), 256>>>();
    tc_gemm<<<dim3(32, 2, NB), 256, TCG_SMEM>>>(1, nullptr, nullptr, out, b_out);  // out (tf32 TC)
}

// round 10
// speedup vs baseline: 1.5048x; 1.0357x over previous
#include <cuda_runtime.h>
#include <math.h>
#include <stdint.h>

#define NB 16
#define GN 4096

// ---------------- scratch (allocation-free: device globals) ----------------
__device__ float g_qkv[NB * 768 * 4096];   // [b][o][n] (q-hat in place rows 0-255, k 256-511, v 512-767)
__device__ float g_ctxp[16 * 64 * 4096];   // [split][bh][d*64+e]
__device__ float g_ctx[64 * 4096];         // [bh][d*64+e] reduced
__device__ float g_M[NB * 256 * 256];      // folded weight
__device__ float g_kmax[NB * 256];
__device__ float g_kinv[NB * 256];

// ---------------- tf32 helpers ----------------
__device__ __forceinline__ float f2tf32(float f) {
    uint32_t u;
    asm("cvt.rna.tf32.f32 %0, %1;" : "=r"(u) : "f"(f));
    return __uint_as_float(u);
}
__device__ __forceinline__ void mma_tf32(float* d, const uint32_t* a, const uint32_t* bb) {
    asm volatile(
        "mma.sync.aligned.m16n8k8.row.col.f32.tf32.tf32.f32 "
        "{%0,%1,%2,%3}, {%4,%5,%6,%7}, {%8,%9}, {%0,%1,%2,%3};"
        : "+f"(d[0]), "+f"(d[1]), "+f"(d[2]), "+f"(d[3])
        : "r"(a[0]), "r"(a[1]), "r"(a[2]), "r"(a[3]), "r"(bb[0]), "r"(bb[1]));
}

// ---------------- fragment-layout SMEM geometry ----------------
#define AFS 132                    // A' per-(ks,tile16) block stride, floats (16B-aligned blocks)
#define ABUF (32 * AFS)            // 4224 floats / buffer
#define BTS 66                     // B' per-n8-tile stride
#define BKS (16 * BTS + 8)         // 1064 floats per ks slab (pad 8 spreads ks across banks)
#define BBUF (4 * BKS)             // 4256 floats / buffer
#define CLD 132                    // epilogue C stage row stride
#define TCG_SMEM ((2 * (ABUF + BBUF)) * 4)   // 67840 bytes

// C[M,4096] = A[M,256] @ B[256,4096]  (tf32 mma.sync, fragment-layout SMEM)
// mode 0: A=w_qkv, B=x[b], C=g_qkv     mode 1: A=g_M[b], B=q-hat rows of g_qkv, C=out (+bias)
__global__ __launch_bounds__(256, 2) void tc_gemm(int mode,
                                                  const float* __restrict__ w,
                                                  const float* __restrict__ xp,
                                                  float* __restrict__ outp,
                                                  const float* __restrict__ bias) {
    extern __shared__ float smem[];
    float* As0 = smem;
    float* Bs0 = smem + 2 * ABUF;

    const int t = threadIdx.x;
    const int lid = t & 31, wid = t >> 5;
    const int wm = wid >> 1, wn = wid & 1;
    const int b = blockIdx.z, n0 = blockIdx.x * 128, m0 = blockIdx.y * 128;

    const float* A;
    const float* B;
    float* C;
    if (mode == 0) {
        A = w + (size_t)m0 * 256;
        B = xp + (size_t)b * (256ull * 4096) + n0;
        C = g_qkv + (size_t)b * (768ull * 4096) + (size_t)m0 * 4096 + n0;
    } else {
        A = g_M + (size_t)b * 65536 + (size_t)m0 * 256;
        B = g_qkv + (size_t)b * (768ull * 4096) + n0;
        C = outp + (size_t)b * (256ull * 4096) + (size_t)m0 * 4096 + n0;
    }

    // ---- writer mappings ----
    // A: thread holds rows (t>>3)+32j (j=0..3), k = (t&7)*4 .. +3   (LDG.128 coalesced per row)
    const int arow = t >> 3;
    const int akb = (t & 7) * 4;
    const int aks = akb >> 3;
    const int akr = (akb >> 2) & 1;
    // B: thread holds k-row t>>3, cols (t&7)*16 .. +15  (4x LDG.128 coalesced)
    const int bkr = t >> 3;
    const int bcb = (t & 7) * 16;
    const int bks = bkr >> 3;
    const int bk83 = bkr & 3;
    const int bkrg = (bkr >> 2) & 1;

    float acc[2][8][4];
#pragma unroll
    for (int mi = 0; mi < 2; mi++)
#pragma unroll
        for (int nj = 0; nj < 8; nj++)
#pragma unroll
            for (int q = 0; q < 4; q++) acc[mi][nj][q] = 0.f;

    // ---- store one chunk's registers into fragment-layout buffers ----
    auto sts_chunk = [&](float* Ab, float* Bb, const float4* av, const float4* bv) {
#pragma unroll
        for (int j = 0; j < 4; j++) {
            int row = arow + j * 32;
            int r = row & 15, tile = row >> 4;
            float* d = Ab + (aks * 8 + tile) * AFS + (r & 7) * 16 + (r >> 3) + 2 * akr;
            d[0]  = f2tf32(av[j].x);
            d[4]  = f2tf32(av[j].y);
            d[8]  = f2tf32(av[j].z);
            d[12] = f2tf32(av[j].w);
        }
        float* dB = Bb + bks * BKS + bk83 * 2 + bkrg;
#pragma unroll
        for (int i = 0; i < 4; i++) {
            float c0 = f2tf32(bv[i].x), c1 = f2tf32(bv[i].y);
            float c2 = f2tf32(bv[i].z), c3 = f2tf32(bv[i].w);
            int col = bcb + i * 4;
            dB[(col >> 3) * BTS + (col & 7) * 8]                   = c0;
            dB[((col + 1) >> 3) * BTS + ((col + 1) & 7) * 8]       = c1;
            dB[((col + 2) >> 3) * BTS + ((col + 2) & 7) * 8]       = c2;
            dB[((col + 3) >> 3) * BTS + ((col + 3) & 7) * 8]       = c3;
        }
    };

    // preload chunk 0
    {
        float4 av[4], bv[4];
#pragma unroll
        for (int j = 0; j < 4; j++)
            av[j] = *(const float4*)(A + (size_t)(arow + j * 32) * 256 + akb);
#pragma unroll
        for (int i = 0; i < 4; i++)
            bv[i] = *(const float4*)(B + (size_t)bkr * 4096 + bcb + i * 4);
        sts_chunk(As0, Bs0, av, bv);
    }
    __syncthreads();

    for (int c = 0; c < 8; c++) {
        const int s = c & 1;
        float4 av[4], bv[4];
        if (c < 7) {
            const int k0 = (c + 1) * 32;
#pragma unroll
            for (int j = 0; j < 4; j++)
                av[j] = *(const float4*)(A + (size_t)(arow + j * 32) * 256 + k0 + akb);
#pragma unroll
            for (int i = 0; i < 4; i++)
                bv[i] = *(const float4*)(B + (size_t)(k0 + bkr) * 4096 + bcb + i * 4);
        }
        const float* Ab = As0 + s * ABUF;
        const float* Bb = Bs0 + s * BBUF;
#pragma unroll
        for (int ks = 0; ks < 4; ks++) {
            uint32_t af[2][4];
#pragma unroll
            for (int mi = 0; mi < 2; mi++) {
                const uint4 v = *(const uint4*)(Ab + (ks * 8 + wm * 2 + mi) * AFS + lid * 4);
                af[mi][0] = v.x; af[mi][1] = v.y; af[mi][2] = v.z; af[mi][3] = v.w;
            }
#pragma unroll
            for (int nj = 0; nj < 8; nj++) {
                const uint2 bvv = *(const uint2*)(Bb + ks * BKS + (wn * 8 + nj) * BTS + lid * 2);
                uint32_t bf[2] = {bvv.x, bvv.y};
                mma_tf32(acc[0][nj], af[0], bf);
                mma_tf32(acc[1][nj], af[1], bf);
            }
        }
        if (c < 7) {
            const int s2 = s ^ 1;
            sts_chunk(As0 + s2 * ABUF, Bs0 + s2 * BBUF, av, bv);
            __syncthreads();
        }
    }

    // ---- epilogue: stage C tile in smem, coalesced float4 out ----
    __syncthreads();
    float* Cs = smem;   // 128 x CLD = 16896 floats <= 16960 available
    const int gid = lid >> 2, tig = lid & 3;
#pragma unroll
    for (int mi = 0; mi < 2; mi++)
#pragma unroll
        for (int nj = 0; nj < 8; nj++) {
            int row = wm * 32 + mi * 16 + gid;
            int col = wn * 64 + nj * 8 + 2 * tig;
            Cs[row * CLD + col]           = acc[mi][nj][0];
            Cs[row * CLD + col + 1]       = acc[mi][nj][1];
            Cs[(row + 8) * CLD + col]     = acc[mi][nj][2];
            Cs[(row + 8) * CLD + col + 1] = acc[mi][nj][3];
        }
    __syncthreads();
    {
        const int r = t >> 1, h = (t & 1) * 64;
        const float bsv = bias ? bias[m0 + r] : 0.f;
        float* crow = C + (size_t)r * 4096 + h;
        const float* srow = Cs + r * CLD + h;
#pragma unroll
        for (int j = 0; j < 16; j++) {
            float4 v = *(const float4*)(srow + j * 4);
            v.x += bsv; v.y += bsv; v.z += bsv; v.w += bsv;
            *(float4*)(crow + j * 4) = v;
        }
    }
}

// ---------------- K2: k-row softmax stats (single-pass online) ----------------
__global__ __launch_bounds__(256) void kstats_kernel() {
    int row = blockIdx.x;
    int b = row >> 8, hd = row & 255;
    const float* kp = g_qkv + ((size_t)(b * 768 + 256 + hd)) * GN;
    __shared__ float sm[256], ss[256];
    int t = threadIdx.x;
    float m = -1e30f, s = 0.f;
    for (int i = t; i < 1024; i += 256) {
        float4 v = *(const float4*)(kp + i * 4);
        float lm = fmaxf(fmaxf(v.x, v.y), fmaxf(v.z, v.w));
        if (lm > m) { s *= expf(m - lm); m = lm; }
        s += expf(v.x - m) + expf(v.y - m) + expf(v.z - m) + expf(v.w - m);
    }
    sm[t] = m; ss[t] = s; __syncthreads();
    for (int st = 128; st > 0; st >>= 1) {
        if (t < st) {
            float m2 = sm[t + st], s2 = ss[t + st];
            float M = fmaxf(sm[t], m2);
            ss[t] = ss[t] * expf(sm[t] - M) + s2 * expf(m2 - M);
            sm[t] = M;
        }
        __syncthreads();
    }
    if (t == 0) { g_kmax[row] = sm[0]; g_kinv[row] = 1.f / ss[0]; }
}

// ---------------- K3: partial contexts (16-way deterministic split) ----------------
__global__ __launch_bounds__(256) void ctx_kernel() {
    int s = blockIdx.x, bh = blockIdx.y;
    int b = bh >> 2, h = bh & 3;
    const float* kb = g_qkv + ((size_t)(b * 768 + 256 + h * 64)) * GN + s * 256;
    const float* vb = g_qkv + ((size_t)(b * 768 + 512 + h * 64)) * GN + s * 256;
    __shared__ float ks[64][33];
    __shared__ float vs[64][33];
    int t = threadIdx.x;
    int tx = t & 15, ty = t >> 4;
    float acc[4][4];
#pragma unroll
    for (int i = 0; i < 4; i++)
#pragma unroll
        for (int j = 0; j < 4; j++) acc[i][j] = 0.f;

    for (int c = 0; c < 256; c += 32) {
        __syncthreads();
        for (int i = t; i < 512; i += 256) {
            int d = i >> 3, nn = (i & 7) * 4;
            float4 kv = *(const float4*)(kb + (size_t)d * GN + c + nn);
            float mx = g_kmax[bh * 64 + d], iv = g_kinv[bh * 64 + d];
            ks[d][nn + 0] = expf(kv.x - mx) * iv;
            ks[d][nn + 1] = expf(kv.y - mx) * iv;
            ks[d][nn + 2] = expf(kv.z - mx) * iv;
            ks[d][nn + 3] = expf(kv.w - mx) * iv;
            float4 vv = *(const float4*)(vb + (size_t)d * GN + c + nn);
            vs[d][nn + 0] = vv.x; vs[d][nn + 1] = vv.y;
            vs[d][nn + 2] = vv.z; vs[d][nn + 3] = vv.w;
        }
        __syncthreads();
#pragma unroll 8
        for (int nn = 0; nn < 32; nn++) {
            float ar[4], br[4];
#pragma unroll
            for (int i = 0; i < 4; i++) ar[i] = ks[ty * 4 + i][nn];
#pragma unroll
            for (int j = 0; j < 4; j++) br[j] = vs[tx * 4 + j][nn];
#pragma unroll
            for (int i = 0; i < 4; i++)
#pragma unroll
                for (int j = 0; j < 4; j++)
                    acc[i][j] = fmaf(ar[i], br[j], acc[i][j]);
        }
    }
    float* cp = g_ctxp + ((size_t)(s * 64 + bh)) * 4096;
#pragma unroll
    for (int i = 0; i < 4; i++)
        *(float4*)(cp + (ty * 4 + i) * 64 + tx * 4) =
            make_float4(acc[i][0], acc[i][1], acc[i][2], acc[i][3]);
}

// ---------------- K3b: reduce split partials ----------------
__global__ __launch_bounds__(256) void ctxsum_kernel() {
    int bh = blockIdx.x, t = threadIdx.x;
    for (int i = t * 4; i < 4096; i += 1024) {
        float4 a = make_float4(0.f, 0.f, 0.f, 0.f);
#pragma unroll
        for (int sp = 0; sp < 16; sp++) {
            float4 v = *(const float4*)(g_ctxp + ((size_t)(sp * 64 + bh)) * 4096 + i);
            a.x += v.x; a.y += v.y; a.z += v.z; a.w += v.w;
        }
        *(float4*)(g_ctx + (size_t)bh * 4096 + i) = a;
    }
}

// ---------------- K4: fold ctx into W_out ----------------
__global__ __launch_bounds__(256) void mmat_kernel(const float* __restrict__ w_out) {
    int oq = blockIdx.x, bh = blockIdx.y;
    int b = bh >> 2, h = bh & 3;
    __shared__ float ctx[64][65];
    int t = threadIdx.x;
    for (int i = t * 4; i < 4096; i += 1024) {
        float4 v = *(const float4*)(g_ctx + (size_t)bh * 4096 + i);
        ctx[i >> 6][i & 63] = v.x;
        ctx[(i + 1) >> 6][(i + 1) & 63] = v.y;
        ctx[(i + 2) >> 6][(i + 2) & 63] = v.z;
        ctx[(i + 3) >> 6][(i + 3) & 63] = v.w;
    }
    __syncthreads();
    int o = oq * 64 + (t >> 2);
    int d0 = (t & 3) * 16;
    float w[64];
    const float* wp = w_out + o * 256 + h * 64;
#pragma unroll
    for (int e = 0; e < 64; e += 4) {
        float4 v = *(const float4*)(wp + e);
        w[e] = v.x; w[e + 1] = v.y; w[e + 2] = v.z; w[e + 3] = v.w;
    }
    float* Mp = g_M + (size_t)b * 65536 + o * 256 + h * 64;
    for (int d = d0; d < d0 + 16; d++) {
        float a = 0.f;
#pragma unroll
        for (int e = 0; e < 64; e++) a = fmaf(w[e], ctx[d][e], a);
        Mp[d] = a;
    }
}

// ---------------- K5: q softmax over d, in place, times SCALE ----------------
__global__ __launch_bounds__(256) void qnorm_kernel() {
    int nt = blockIdx.x;
    int bh = blockIdx.y;
    int b = bh >> 2, h = bh & 3;
    float* qb = g_qkv + ((size_t)(b * 768 + h * 64)) * GN + nt * 64;
    __shared__ float tile[64][68];
    __shared__ float red[4][64];
    __shared__ float cmax[64];
    __shared__ float cfac[64];
    int t = threadIdx.x;
    int d = t >> 2, c0 = (t & 3) * 16;
#pragma unroll
    for (int i = 0; i < 4; i++) {
        float4 v = *(const float4*)(qb + (size_t)d * GN + c0 + i * 4);
        *(float4*)&tile[d][c0 + i * 4] = v;
    }
    __syncthreads();
    int col = t & 63, seg = t >> 6;
    float m = -1e30f;
    for (int r = seg * 16; r < seg * 16 + 16; r++) m = fmaxf(m, tile[r][col]);
    red[seg][col] = m;
    __syncthreads();
    if (seg == 0)
        cmax[col] = fmaxf(fmaxf(red[0][col], red[1][col]), fmaxf(red[2][col], red[3][col]));
    __syncthreads();
    float mm = cmax[col];
    float ssum = 0.f;
    for (int r = seg * 16; r < seg * 16 + 16; r++) {
        float e = expf(tile[r][col] - mm);
        tile[r][col] = e;
        ssum += e;
    }
    red[seg][col] = ssum;
    __syncthreads();
    if (seg == 0)
        cfac[col] = 0.125f / (red[0][col] + red[1][col] + red[2][col] + red[3][col]);
    __syncthreads();
#pragma unroll
    for (int i = 0; i < 4; i++) {
        int c = c0 + i * 4;
        float4 v = *(float4*)&tile[d][c];
        v.x *= cfac[c]; v.y *= cfac[c + 1]; v.z *= cfac[c + 2]; v.w *= cfac[c + 3];
        *(float4*)(qb + (size_t)d * GN + c) = v;
    }
}

extern "C" void kernel_launch(void* const* d_in, const int* in_sizes, int n_in,
                              void* d_out, int out_size) {
    const float* x     = (const float*)d_in[0];
    const float* w_qkv = (const float*)d_in[1];
    const float* w_out = (const float*)d_in[2];
    const float* b_out = (const float*)d_in[3];
    float* out = (float*)d_out;

    cudaFuncSetAttribute(tc_gemm, cudaFuncAttributeMaxDynamicSharedMemorySize, TCG_SMEM);

    tc_gemm<<<dim3(32, 6, NB), 256, TCG_SMEM>>>(0, w_qkv, x, nullptr, nullptr);
    kstats_kernel<<<4096, 256>>>();
    ctx_kernel<<<dim3(16, 64), 256>>>();
    ctxsum_kernel<<<64, 256>>>();
    mmat_kernel<<<dim3(4, 64), 256>>>(w_out);
    qnorm_kernel<<<dim3(64, 64), 256>>>();
    tc_gemm<<<dim3(32, 2, NB), 256, TCG_SMEM>>>(1, nullptr, nullptr, out, b_out);
}

// round 15
// speedup vs baseline: 1.5537x; 1.0325x over previous
#include <cuda_runtime.h>
#include <math.h>
#include <stdint.h>

#define NB 16
#define GN 4096

// ---------------- scratch (allocation-free: device globals) ----------------
__device__ float g_qkv[NB * 768 * 4096];   // [b][o][n] (q-hat rows 0-255, k 256-511, v 512-767)
__device__ float g_ctxp[16 * 64 * 4096];   // [split][bh][d*64+e]
__device__ float g_M[NB * 256 * 256];      // folded weight
__device__ float g_kmax[NB * 256];
__device__ float g_kinv[NB * 256];

// ---------------- tf32 helpers ----------------
__device__ __forceinline__ float f2tf32(float f) {
    uint32_t u;
    asm("cvt.rna.tf32.f32 %0, %1;" : "=r"(u) : "f"(f));
    return __uint_as_float(u);
}
__device__ __forceinline__ void mma_tf32(float* d, const uint32_t* a, const uint32_t* bb) {
    asm volatile(
        "mma.sync.aligned.m16n8k8.row.col.f32.tf32.tf32.f32 "
        "{%0,%1,%2,%3}, {%4,%5,%6,%7}, {%8,%9}, {%0,%1,%2,%3};"
        : "+f"(d[0]), "+f"(d[1]), "+f"(d[2]), "+f"(d[3])
        : "r"(a[0]), "r"(a[1]), "r"(a[2]), "r"(a[3]), "r"(bb[0]), "r"(bb[1]));
}

// ---------------- fragment-layout SMEM geometry ----------------
#define AFS 132
#define ABUF (32 * AFS)
#define BTS 66
#define BKS (16 * BTS + 8)
#define BBUF (4 * BKS)
#define CLD 132
#define TCG_SMEM ((2 * (ABUF + BBUF)) * 4)   // 67840 bytes

// C[128,4096-tile] = A[128,256] @ B[256,4096]  (tf32 mma.sync)
// mode 0: qkv k/v rows (m_global = 256 + by*128), C=g_qkv
// mode 2: qkv q rows   (m_global = by*128) + FUSED softmax-over-d epilogue (writes q-hat*SCALE)
// mode 1: out rows     (A=g_M[b], B=q-hat, C=out, +bias)
__global__ __launch_bounds__(256, 2) void tc_gemm(int mode,
                                                  const float* __restrict__ w,
                                                  const float* __restrict__ xp,
                                                  float* __restrict__ outp,
                                                  const float* __restrict__ bias) {
    extern __shared__ float smem[];
    float* As0 = smem;
    float* Bs0 = smem + 2 * ABUF;

    const int t = threadIdx.x;
    const int lid = t & 31, wid = t >> 5;
    const int wm = wid >> 1, wn = wid & 1;
    const int b = blockIdx.z, n0 = blockIdx.x * 128;

    const float* A;
    const float* B;
    float* C;
    if (mode == 1) {
        const int m0 = blockIdx.y * 128;
        A = g_M + (size_t)b * 65536 + (size_t)m0 * 256;
        B = g_qkv + (size_t)b * (768ull * 4096) + n0;
        C = outp + (size_t)b * (256ull * 4096) + (size_t)m0 * 4096 + n0;
    } else {
        const int mg = (mode == 0 ? 256 : 0) + blockIdx.y * 128;
        A = w + (size_t)mg * 256;
        B = xp + (size_t)b * (256ull * 4096) + n0;
        C = g_qkv + (size_t)b * (768ull * 4096) + (size_t)mg * 4096 + n0;
    }

    // writer mappings
    const int arow = t >> 3;
    const int akb = (t & 7) * 4;
    const int aks = akb >> 3;
    const int akr = (akb >> 2) & 1;
    const int bkr = t >> 3;
    const int bcb = (t & 7) * 16;
    const int bks = bkr >> 3;
    const int bk83 = bkr & 3;
    const int bkrg = (bkr >> 2) & 1;

    float acc[2][8][4];
#pragma unroll
    for (int mi = 0; mi < 2; mi++)
#pragma unroll
        for (int nj = 0; nj < 8; nj++)
#pragma unroll
            for (int q = 0; q < 4; q++) acc[mi][nj][q] = 0.f;

    auto sts_chunk = [&](float* Ab, float* Bb, const float4* av, const float4* bv) {
#pragma unroll
        for (int j = 0; j < 4; j++) {
            int row = arow + j * 32;
            int r = row & 15, tile = row >> 4;
            float* d = Ab + (aks * 8 + tile) * AFS + (r & 7) * 16 + (r >> 3) + 2 * akr;
            d[0]  = f2tf32(av[j].x);
            d[4]  = f2tf32(av[j].y);
            d[8]  = f2tf32(av[j].z);
            d[12] = f2tf32(av[j].w);
        }
        float* dB = Bb + bks * BKS + bk83 * 2 + bkrg;
#pragma unroll
        for (int i = 0; i < 4; i++) {
            float c0 = f2tf32(bv[i].x), c1 = f2tf32(bv[i].y);
            float c2 = f2tf32(bv[i].z), c3 = f2tf32(bv[i].w);
            int col = bcb + i * 4;
            dB[(col >> 3) * BTS + (col & 7) * 8]             = c0;
            dB[((col + 1) >> 3) * BTS + ((col + 1) & 7) * 8] = c1;
            dB[((col + 2) >> 3) * BTS + ((col + 2) & 7) * 8] = c2;
            dB[((col + 3) >> 3) * BTS + ((col + 3) & 7) * 8] = c3;
        }
    };

    {   // preload chunk 0
        float4 av[4], bv[4];
#pragma unroll
        for (int j = 0; j < 4; j++)
            av[j] = *(const float4*)(A + (size_t)(arow + j * 32) * 256 + akb);
#pragma unroll
        for (int i = 0; i < 4; i++)
            bv[i] = *(const float4*)(B + (size_t)bkr * 4096 + bcb + i * 4);
        sts_chunk(As0, Bs0, av, bv);
    }
    __syncthreads();

    for (int c = 0; c < 8; c++) {
        const int s = c & 1;
        float4 av[4], bv[4];
        if (c < 7) {
            const int k0 = (c + 1) * 32;
#pragma unroll
            for (int j = 0; j < 4; j++)
                av[j] = *(const float4*)(A + (size_t)(arow + j * 32) * 256 + k0 + akb);
#pragma unroll
            for (int i = 0; i < 4; i++)
                bv[i] = *(const float4*)(B + (size_t)(k0 + bkr) * 4096 + bcb + i * 4);
        }
        const float* Ab = As0 + s * ABUF;
        const float* Bb = Bs0 + s * BBUF;
#pragma unroll
        for (int ks = 0; ks < 4; ks++) {
            uint32_t af[2][4];
#pragma unroll
            for (int mi = 0; mi < 2; mi++) {
                const uint4 v = *(const uint4*)(Ab + (ks * 8 + wm * 2 + mi) * AFS + lid * 4);
                af[mi][0] = v.x; af[mi][1] = v.y; af[mi][2] = v.z; af[mi][3] = v.w;
            }
#pragma unroll
            for (int nj = 0; nj < 8; nj++) {
                const uint2 bvv = *(const uint2*)(Bb + ks * BKS + (wn * 8 + nj) * BTS + lid * 2);
                uint32_t bf[2] = {bvv.x, bvv.y};
                mma_tf32(acc[0][nj], af[0], bf);
                mma_tf32(acc[1][nj], af[1], bf);
            }
        }
        if (c < 7) {
            const int s2 = s ^ 1;
            sts_chunk(As0 + s2 * ABUF, Bs0 + s2 * BBUF, av, bv);
            __syncthreads();
        }
    }

    // ---- epilogue: stage C tile in smem ----
    __syncthreads();
    float* Cs = smem;
    const int gid = lid >> 2, tig = lid & 3;
#pragma unroll
    for (int mi = 0; mi < 2; mi++)
#pragma unroll
        for (int nj = 0; nj < 8; nj++) {
            int row = wm * 32 + mi * 16 + gid;
            int col = wn * 64 + nj * 8 + 2 * tig;
            Cs[row * CLD + col]           = acc[mi][nj][0];
            Cs[row * CLD + col + 1]       = acc[mi][nj][1];
            Cs[(row + 8) * CLD + col]     = acc[mi][nj][2];
            Cs[(row + 8) * CLD + col + 1] = acc[mi][nj][3];
        }
    __syncthreads();

    if (mode == 2) {
        // fused q softmax over d: tile rows = 2 heads x 64 d; one thread per (head, col)
        const int head = t >> 7, col = t & 127;
        float* base = Cs + (head * 64) * CLD + col;
        float mx = -1e30f;
#pragma unroll 8
        for (int r = 0; r < 64; r++) mx = fmaxf(mx, base[r * CLD]);
        float s = 0.f;
#pragma unroll 8
        for (int r = 0; r < 64; r++) {
            float e = __expf(base[r * CLD] - mx);
            base[r * CLD] = e;
            s += e;
        }
        const float f = 0.125f / s;
#pragma unroll 8
        for (int r = 0; r < 64; r++) base[r * CLD] *= f;
        __syncthreads();
    }

    {   // coalesced writeback
        const int r = t >> 1, h = (t & 1) * 64;
        const float bsv = (mode == 1 && bias) ? bias[(blockIdx.y * 128) + r] : 0.f;
        float* crow = C + (size_t)r * 4096 + h;
        const float* srow = Cs + r * CLD + h;
#pragma unroll
        for (int j = 0; j < 16; j++) {
            float4 v = *(const float4*)(srow + j * 4);
            v.x += bsv; v.y += bsv; v.z += bsv; v.w += bsv;
            *(float4*)(crow + j * 4) = v;
        }
    }
}

// ---------------- K2: k-row softmax stats (single-pass online) ----------------
__global__ __launch_bounds__(256) void kstats_kernel() {
    int row = blockIdx.x;
    int b = row >> 8, hd = row & 255;
    const float* kp = g_qkv + ((size_t)(b * 768 + 256 + hd)) * GN;
    __shared__ float sm[256], ss[256];
    int t = threadIdx.x;
    float m = -1e30f, s = 0.f;
    for (int i = t; i < 1024; i += 256) {
        float4 v = *(const float4*)(kp + i * 4);
        float lm = fmaxf(fmaxf(v.x, v.y), fmaxf(v.z, v.w));
        if (lm > m) { s *= __expf(m - lm); m = lm; }
        s += __expf(v.x - m) + __expf(v.y - m) + __expf(v.z - m) + __expf(v.w - m);
    }
    sm[t] = m; ss[t] = s; __syncthreads();
    for (int st = 128; st > 0; st >>= 1) {
        if (t < st) {
            float m2 = sm[t + st], s2 = ss[t + st];
            float M = fmaxf(sm[t], m2);
            ss[t] = ss[t] * __expf(sm[t] - M) + s2 * __expf(m2 - M);
            sm[t] = M;
        }
        __syncthreads();
    }
    if (t == 0) { g_kmax[row] = sm[0]; g_kinv[row] = 1.f / ss[0]; }
}

// ---------------- K3: partial contexts (16-way deterministic split) ----------------
__global__ __launch_bounds__(256) void ctx_kernel() {
    int s = blockIdx.x, bh = blockIdx.y;
    int b = bh >> 2, h = bh & 3;
    const float* kb = g_qkv + ((size_t)(b * 768 + 256 + h * 64)) * GN + s * 256;
    const float* vb = g_qkv + ((size_t)(b * 768 + 512 + h * 64)) * GN + s * 256;
    __shared__ float ks[64][33];
    __shared__ float vs[64][33];
    int t = threadIdx.x;
    int tx = t & 15, ty = t >> 4;
    float acc[4][4];
#pragma unroll
    for (int i = 0; i < 4; i++)
#pragma unroll
        for (int j = 0; j < 4; j++) acc[i][j] = 0.f;

    for (int c = 0; c < 256; c += 32) {
        __syncthreads();
        for (int i = t; i < 512; i += 256) {
            int d = i >> 3, nn = (i & 7) * 4;
            float4 kv = *(const float4*)(kb + (size_t)d * GN + c + nn);
            float mx = g_kmax[bh * 64 + d], iv = g_kinv[bh * 64 + d];
            ks[d][nn + 0] = __expf(kv.x - mx) * iv;
            ks[d][nn + 1] = __expf(kv.y - mx) * iv;
            ks[d][nn + 2] = __expf(kv.z - mx) * iv;
            ks[d][nn + 3] = __expf(kv.w - mx) * iv;
            float4 vv = *(const float4*)(vb + (size_t)d * GN + c + nn);
            vs[d][nn + 0] = vv.x; vs[d][nn + 1] = vv.y;
            vs[d][nn + 2] = vv.z; vs[d][nn + 3] = vv.w;
        }
        __syncthreads();
#pragma unroll 8
        for (int nn = 0; nn < 32; nn++) {
            float ar[4], br[4];
#pragma unroll
            for (int i = 0; i < 4; i++) ar[i] = ks[ty * 4 + i][nn];
#pragma unroll
            for (int j = 0; j < 4; j++) br[j] = vs[tx * 4 + j][nn];
#pragma unroll
            for (int i = 0; i < 4; i++)
#pragma unroll
                for (int j = 0; j < 4; j++)
                    acc[i][j] = fmaf(ar[i], br[j], acc[i][j]);
        }
    }
    float* cp = g_ctxp + ((size_t)(s * 64 + bh)) * 4096;
#pragma unroll
    for (int i = 0; i < 4; i++)
        *(float4*)(cp + (ty * 4 + i) * 64 + tx * 4) =
            make_float4(acc[i][0], acc[i][1], acc[i][2], acc[i][3]);
}

// ---------------- K4: reduce partials + fold ctx into W_out (one kernel) ----------------
__global__ __launch_bounds__(256) void mmat_kernel(const float* __restrict__ w_out) {
    int bh = blockIdx.x;
    int b = bh >> 2, h = bh & 3;
    __shared__ float ctx[64][65];
    int t = threadIdx.x;
    for (int i = t * 4; i < 4096; i += 1024) {
        float4 a = make_float4(0.f, 0.f, 0.f, 0.f);
#pragma unroll
        for (int sp = 0; sp < 16; sp++) {
            float4 v = *(const float4*)(g_ctxp + ((size_t)(sp * 64 + bh)) * 4096 + i);
            a.x += v.x; a.y += v.y; a.z += v.z; a.w += v.w;
        }
        int d = i >> 6, e = i & 63;
        ctx[d][e] = a.x; ctx[d][e + 1] = a.y; ctx[d][e + 2] = a.z; ctx[d][e + 3] = a.w;
    }
    __syncthreads();
    int o = t;
    float w[64];
    const float* wp = w_out + o * 256 + h * 64;
#pragma unroll
    for (int e = 0; e < 64; e += 4) {
        float4 v = *(const float4*)(wp + e);
        w[e] = v.x; w[e + 1] = v.y; w[e + 2] = v.z; w[e + 3] = v.w;
    }
    float* Mp = g_M + (size_t)b * 65536 + o * 256 + h * 64;
#pragma unroll 2
    for (int d = 0; d < 64; d++) {
        float a = 0.f;
#pragma unroll
        for (int e = 0; e < 64; e++) a = fmaf(w[e], ctx[d][e], a);
        Mp[d] = a;
    }
}

extern "C" void kernel_launch(void* const* d_in, const int* in_sizes, int n_in,
                              void* d_out, int out_size) {
    const float* x     = (const float*)d_in[0];
    const float* w_qkv = (const float*)d_in[1];
    const float* w_out = (const float*)d_in[2];
    const float* b_out = (const float*)d_in[3];
    float* out = (float*)d_out;

    cudaFuncSetAttribute(tc_gemm, cudaFuncAttributeMaxDynamicSharedMemorySize, TCG_SMEM);

    tc_gemm<<<dim3(32, 4, NB), 256, TCG_SMEM>>>(0, w_qkv, x, nullptr, nullptr);  // k,v rows
    kstats_kernel<<<4096, 256>>>();
    ctx_kernel<<<dim3(16, 64), 256>>>();
    tc_gemm<<<dim3(32, 2, NB), 256, TCG_SMEM>>>(2, w_qkv, x, nullptr, nullptr);  // q rows + fused softmax (profiled slot 3)
    mmat_kernel<<<64, 256>>>(w_out);
    tc_gemm<<<dim3(32, 2, NB), 256, TCG_SMEM>>>(1, nullptr, nullptr, out, b_out);
}